// round 3
// baseline (speedup 1.0000x reference)
#include <cuda_runtime.h>

#define MARGIN 0.1f
constexpr int Bn = 8192;
constexpr int Ln = 1024;
constexpr int THREADS = 256;   // 256 threads * 4 floats = 1024 = L

// Deterministic global accumulators (Q32.32 fixed point, two's complement).
// Integer atomics are associative -> bit-identical result every replay.
// The last block drains them with atomicExch, leaving zeros for next replay.
__device__ unsigned long long g_acc_bce;
__device__ unsigned long long g_acc_hinge;
__device__ unsigned long long g_acc_valid;   // plain integer count
__device__ unsigned long long g_acc_sim;
__device__ unsigned int       g_done;

__global__ void __launch_bounds__(THREADS)
fused_kernel(const float4* __restrict__ scores4,
             const int*    __restrict__ lens,
             const float4* __restrict__ labels4,
             const float*  __restrict__ sim,
             float*        __restrict__ out)
{
    const int row = blockIdx.x;
    const int tid = threadIdx.x;
    const int len = lens[row];

    // One float4 of scores + labels per thread; kept in registers for both passes.
    const float4 s4 = scores4[row * THREADS + tid];
    const float4 l4 = labels4[row * THREADS + tid];
    const float sv[4] = {s4.x, s4.y, s4.z, s4.w};
    const float lv[4] = {l4.x, l4.y, l4.z, l4.w};
    const int base = tid * 4;

    float bce = 0.f, pcnt = 0.f, psum = 0.f;
#pragma unroll
    for (int k = 0; k < 4; ++k) {
        const bool in = (base + k < len);
        const float s = sv[k];
        const float l = lv[k];
        const float lp  = fmaxf(__logf(s),        -100.f);
        const float l1m = fmaxf(__logf(1.0f - s), -100.f);
        const float el  = -(l * lp + (1.0f - l) * l1m);
        bce += in ? el : 0.0f;
        const bool pos = in && (l == 1.0f);
        pcnt += pos ? 1.0f : 0.0f;
        psum += pos ? s    : 0.0f;
    }

    // ---- block reduction #1 : bce, pos count, pos score sum ----
    const unsigned FULL = 0xffffffffu;
#pragma unroll
    for (int o = 16; o; o >>= 1) {
        bce  += __shfl_down_sync(FULL, bce,  o);
        pcnt += __shfl_down_sync(FULL, pcnt, o);
        psum += __shfl_down_sync(FULL, psum, o);
    }
    __shared__ float sh0[8], sh1[8], sh2[8];
    __shared__ float sh_chosen, sh_bce, sh_pcnt;
    const int w = tid >> 5, lane = tid & 31;
    if (lane == 0) { sh0[w] = bce; sh1[w] = pcnt; sh2[w] = psum; }
    __syncthreads();
    if (tid == 0) {
        float b = 0.f, p = 0.f, q = 0.f;
#pragma unroll
        for (int i = 0; i < 8; ++i) { b += sh0[i]; p += sh1[i]; q += sh2[i]; }
        sh_bce    = b;
        sh_pcnt   = p;
        sh_chosen = (p > 0.f) ? q : -MARGIN;
    }
    __syncthreads();
    const float chosen = sh_chosen;

    // ---- pass 2 from registers: hinge over valid negatives ----
    float hinge = 0.f;
#pragma unroll
    for (int k = 0; k < 4; ++k) {
        const bool neg = (base + k < len) && (lv[k] == 0.0f);
        const float h  = fmaxf(MARGIN + sv[k] - chosen, 0.0f);
        hinge += neg ? h : 0.0f;
    }
#pragma unroll
    for (int o = 16; o; o >>= 1)
        hinge += __shfl_down_sync(FULL, hinge, o);
    __syncthreads();               // protect sh0 reuse
    if (lane == 0) sh0[w] = hinge;
    __syncthreads();

    if (tid == 0) {
        float hsum = 0.f;
#pragma unroll
        for (int i = 0; i < 8; ++i) hsum += sh0[i];
        const float flen = (float)len;
        // bce_per = (bce_el*mask).mean(1) / mask.sum(1) = bce_sum / (L * len)
        const float bce_per = sh_bce / ((float)Ln * flen);
        const float negc = flen - sh_pcnt;
        const bool  val  = (len > 0) && (negc > 0.f);
        const float hrow = val ? hsum / fmaxf(negc, 1.0f) : 0.0f;
        const float srow = sim[row];

        // Q32.32 fixed-point deterministic accumulation (few FP64 ops per block: cheap)
        const double SC = 4294967296.0;
        atomicAdd(&g_acc_bce,   (unsigned long long)__double2ll_rn((double)bce_per * SC));
        atomicAdd(&g_acc_hinge, (unsigned long long)__double2ll_rn((double)hrow    * SC));
        if (val) atomicAdd(&g_acc_valid, 1ULL);
        atomicAdd(&g_acc_sim,   (unsigned long long)__double2ll_rn((double)srow    * SC));

        __threadfence();
        const unsigned ticket = atomicAdd(&g_done, 1u);
        if (ticket == (unsigned)(Bn - 1)) {
            // Last block: drain + reset accumulators (replay-safe), emit outputs.
            const long long ib = (long long)atomicExch(&g_acc_bce,   0ULL);
            const long long ih = (long long)atomicExch(&g_acc_hinge, 0ULL);
            const long long iv = (long long)atomicExch(&g_acc_valid, 0ULL);
            const long long is = (long long)atomicExch(&g_acc_sim,   0ULL);
            atomicExch(&g_done, 0u);

            const double INV = 1.0 / 4294967296.0;
            const double Bsum = (double)ib * INV;
            const double Hsum = (double)ih * INV;
            const double Vcnt = (double)iv;
            const double Ssum = (double)is * INV;

            const double bce_loss   = Bsum / (double)Bn;
            const double hinge_loss = (Vcnt > 0.0) ? Hsum / ((Vcnt > 1.0) ? Vcnt : 1.0) : 0.0;
            const double sim_loss   = -Ssum / (double)Bn;
            const double combined   = hinge_loss + bce_loss + sim_loss;
            out[0] = (float)combined;
            out[1] = (float)hinge_loss;
            out[2] = (float)bce_loss;
            out[3] = (float)sim_loss;
        }
    }
}

extern "C" void kernel_launch(void* const* d_in, const int* in_sizes, int n_in,
                              void* d_out, int out_size)
{
    const float4* scores4 = (const float4*)d_in[0];
    const int*    lens    = (const int*)d_in[1];
    const float4* labels4 = (const float4*)d_in[2];
    const float*  sim     = (const float*)d_in[3];
    float* out = (float*)d_out;

    fused_kernel<<<Bn, THREADS>>>(scores4, lens, labels4, sim, out);
}

// round 4
// speedup vs baseline: 1.0960x; 1.0960x over previous
#include <cuda_runtime.h>

#define MARGIN 0.1f
constexpr int Bn = 8192;
constexpr int Ln = 1024;
constexpr int BLOCKS = 1024;
constexpr int RPB = 8;            // rows per block
constexpr int PAIRS = RPB / 2;    // 2 rows processed concurrently per iteration

// Deterministic Q32.32 fixed-point accumulators (integer atomics = associative).
// Last block drains them with atomicExch -> zeroed for the next graph replay.
__device__ unsigned long long g_acc_bce, g_acc_hinge, g_acc_valid, g_acc_sim;
__device__ unsigned int       g_done;

__global__ void __launch_bounds__(256)
fused_kernel(const float4* __restrict__ scores4,
             const int*    __restrict__ lens,
             const float4* __restrict__ labels4,
             const float*  __restrict__ sim,
             float*        __restrict__ out)
{
    const int tid  = threadIdx.x;
    const int half = tid >> 7;          // which of the 2 concurrent rows
    const int t    = tid & 127;         // thread index within the row
    const int w2   = (tid >> 5) & 3;    // warp index within the half
    const int lane = tid & 31;
    const unsigned FULL = 0xffffffffu;

    __shared__ float shA[2][4], shB[2][4], shC[2][4], shH[2][4];
    __shared__ float sh_chosen[2];
    __shared__ float fin[2][4];

    // per-leader (t==0) accumulators across the block's rows
    float acc_bce = 0.f, acc_h = 0.f, acc_v = 0.f, acc_s = 0.f;

    const int row0 = blockIdx.x * RPB;

    for (int p = 0; p < PAIRS; ++p) {
        const int row  = row0 + p * 2 + half;
        const int len  = lens[row];
        const int base = row * (Ln / 4);      // float4 index of row start
        // 4 independent 16B loads -> MLP 4, coalesced across the 128 threads
        const float4 s0 = __ldcs(&scores4[base + t]);
        const float4 s1 = __ldcs(&scores4[base + t + 128]);
        const float4 l0 = __ldcs(&labels4[base + t]);
        const float4 l1 = __ldcs(&labels4[base + t + 128]);

        const float sv[8] = {s0.x,s0.y,s0.z,s0.w, s1.x,s1.y,s1.z,s1.w};
        const float lv[8] = {l0.x,l0.y,l0.z,l0.w, l1.x,l1.y,l1.z,l1.w};
        const int e0 = 4 * t;

        // ---- pass 1: BCE + positive count / positive score (single log!) ----
        float bce = 0.f, pcnt = 0.f, psum = 0.f;
#pragma unroll
        for (int k = 0; k < 8; ++k) {
            const int  e   = (k < 4) ? (e0 + k) : (512 + e0 + k - 4);
            const bool in  = (e < len);
            const bool lp  = (lv[k] == 1.0f);       // labels are exactly 0/1
            const float sel = lp ? sv[k] : 1.0f - sv[k];
            const float el  = fminf(-__logf(sel), 100.0f);  // = -max(log, -100)
            bce  += in ? el : 0.f;
            const bool pos = in && lp;
            pcnt += pos ? 1.f : 0.f;
            psum += pos ? sv[k] : 0.f;
        }
#pragma unroll
        for (int o = 16; o; o >>= 1) {
            bce  += __shfl_down_sync(FULL, bce,  o);
            pcnt += __shfl_down_sync(FULL, pcnt, o);
            psum += __shfl_down_sync(FULL, psum, o);
        }
        if (lane == 0) { shA[half][w2] = bce; shB[half][w2] = pcnt; shC[half][w2] = psum; }
        __syncthreads();

        if (t == 0) {
            float b = 0.f, pc = 0.f, ps = 0.f;
#pragma unroll
            for (int i = 0; i < 4; ++i) { b += shA[half][i]; pc += shB[half][i]; ps += shC[half][i]; }
            sh_chosen[half] = (pc > 0.f) ? ps : -MARGIN;
            shA[half][0] = b;     // stash row bce total (slot 0 only ever read by t==0)
            shB[half][0] = pc;    // stash row positive count
        }
        __syncthreads();

        // ---- pass 2: hinge over valid negatives (from registers) ----
        const float cm = MARGIN - sh_chosen[half];
        float hinge = 0.f;
#pragma unroll
        for (int k = 0; k < 8; ++k) {
            const int  e   = (k < 4) ? (e0 + k) : (512 + e0 + k - 4);
            const bool neg = (e < len) && (lv[k] != 1.0f);
            const float h  = fmaxf(sv[k] + cm, 0.0f);
            hinge += neg ? h : 0.f;
        }
#pragma unroll
        for (int o = 16; o; o >>= 1)
            hinge += __shfl_down_sync(FULL, hinge, o);
        if (lane == 0) shH[half][w2] = hinge;
        __syncthreads();

        if (t == 0) {
            float hsum = shH[half][0] + shH[half][1] + shH[half][2] + shH[half][3];
            const float b    = shA[half][0];
            const float pc   = shB[half][0];
            const float flen = (float)len;
            const float negc = flen - pc;
            const bool  val  = (len > 0) && (negc > 0.f);
            acc_bce += b / ((float)Ln * flen);            // (bce*mask).mean(1)/mask.sum(1)
            acc_h   += val ? hsum / fmaxf(negc, 1.0f) : 0.f;
            acc_v   += val ? 1.0f : 0.f;
            acc_s   += sim[row];
        }
        // no extra barrier needed: next iteration's shared writes are ordered
        // behind its own __syncthreads(), which waits for t==0.
    }

    if (t == 0) {
        fin[half][0] = acc_bce; fin[half][1] = acc_h;
        fin[half][2] = acc_v;   fin[half][3] = acc_s;
    }
    __syncthreads();

    if (tid == 0) {
        const float bce_b = fin[0][0] + fin[1][0];
        const float h_b   = fin[0][1] + fin[1][1];
        const float v_b   = fin[0][2] + fin[1][2];
        const float s_b   = fin[0][3] + fin[1][3];

        const double SC = 4294967296.0;
        atomicAdd(&g_acc_bce,   (unsigned long long)__double2ll_rn((double)bce_b * SC));
        atomicAdd(&g_acc_hinge, (unsigned long long)__double2ll_rn((double)h_b   * SC));
        atomicAdd(&g_acc_valid, (unsigned long long)(long long)(v_b + 0.5f));
        atomicAdd(&g_acc_sim,   (unsigned long long)__double2ll_rn((double)s_b   * SC));

        __threadfence();
        const unsigned ticket = atomicAdd(&g_done, 1u);
        if (ticket == (unsigned)(BLOCKS - 1)) {
            const long long ib = (long long)atomicExch(&g_acc_bce,   0ULL);
            const long long ih = (long long)atomicExch(&g_acc_hinge, 0ULL);
            const long long iv = (long long)atomicExch(&g_acc_valid, 0ULL);
            const long long is = (long long)atomicExch(&g_acc_sim,   0ULL);
            atomicExch(&g_done, 0u);

            const double INV = 1.0 / 4294967296.0;
            const double Bsum = (double)ib * INV;
            const double Hsum = (double)ih * INV;
            const double Vcnt = (double)iv;
            const double Ssum = (double)is * INV;

            const double bce_loss   = Bsum / (double)Bn;
            const double hinge_loss = (Vcnt > 0.0) ? Hsum / ((Vcnt > 1.0) ? Vcnt : 1.0) : 0.0;
            const double sim_loss   = -Ssum / (double)Bn;
            const double combined   = hinge_loss + bce_loss + sim_loss;
            out[0] = (float)combined;
            out[1] = (float)hinge_loss;
            out[2] = (float)bce_loss;
            out[3] = (float)sim_loss;
        }
    }
}

extern "C" void kernel_launch(void* const* d_in, const int* in_sizes, int n_in,
                              void* d_out, int out_size)
{
    const float4* scores4 = (const float4*)d_in[0];
    const int*    lens    = (const int*)d_in[1];
    const float4* labels4 = (const float4*)d_in[2];
    const float*  sim     = (const float*)d_in[3];
    float* out = (float*)d_out;

    fused_kernel<<<BLOCKS, 256>>>(scores4, lens, labels4, sim, out);
}